// round 14
// baseline (speedup 1.0000x reference)
#include <cuda_runtime.h>
#include <cstdint>

#define NT   2048
#define DIN  1024
#define DHID 4096
#define DOUT 1024
#define NE   8

// ---------------- device scratch ----------------
__device__ int   g_count[NE];
__device__ int   g_hrow[NE][NT];     // hrow = token*2 + k
__device__ float g_cwk[NT][2];       // combine weight, indexed [token][k] (deterministic)
__device__ float g_h[NT * 2][DHID];  // hidden acts (tf32-rounded at write)
__device__ float g_y[NT * 2][DOUT];  // expert outputs before combine
__device__ float g_xr[NT][DIN];      // x (tf32-rounded)

// ---------------- helpers ----------------
__device__ __forceinline__ float rna_f(float f) {
    uint32_t u;
    asm volatile("cvt.rna.tf32.f32 %0, %1;" : "=r"(u) : "f"(f));
    return __uint_as_float(u);
}
__device__ __forceinline__ uint32_t f2tf32(float f) {
    uint32_t u;
    asm volatile("cvt.rna.tf32.f32 %0, %1;" : "=r"(u) : "f"(f));
    return u;
}
__device__ __forceinline__ void mma_tf32(float* c, const uint32_t* a, const uint32_t* b) {
    asm volatile(
        "mma.sync.aligned.m16n8k8.row.col.f32.tf32.tf32.f32 "
        "{%0,%1,%2,%3}, {%4,%5,%6,%7}, {%8,%9}, {%0,%1,%2,%3};"
        : "+f"(c[0]), "+f"(c[1]), "+f"(c[2]), "+f"(c[3])
        : "r"(a[0]), "r"(a[1]), "r"(a[2]), "r"(a[3]), "r"(b[0]), "r"(b[1]));
}
__device__ __forceinline__ void ldsm_x4(uint32_t* r, uint32_t saddr) {
    asm volatile("ldmatrix.sync.aligned.m8n8.x4.shared.b16 {%0,%1,%2,%3}, [%4];"
        : "=r"(r[0]), "=r"(r[1]), "=r"(r[2]), "=r"(r[3]) : "r"(saddr));
}
#define CP_ASYNC16(dst, src) \
    asm volatile("cp.async.cg.shared.global [%0], [%1], 16;\n" :: "r"(dst), "l"(src))
#define CP_COMMIT() asm volatile("cp.async.commit_group;\n" ::)
#define CP_WAIT(n)  asm volatile("cp.async.wait_group %0;\n" :: "n"(n))

// smem layout (identical to R2/R6)
#define A_STRIDE 36     // 32 + 4 pad (floats)
#define B_STRIDE 136    // 128 + 8 pad (floats)
#define A_BUF (128 * A_STRIDE)
#define B_BUF (32 * B_STRIDE)
#define SMEM_FLOATS (2 * A_BUF + 2 * B_BUF)   // 17664 floats = 70656 B

// ---------------- prepass: round x (8 MB, ~4us) ----------------
__global__ void round_x_kernel(const float* __restrict__ src, float* __restrict__ dst) {
    int i = blockIdx.x * blockDim.x + threadIdx.x;
    float4 v = ((const float4*)src)[i];
    v.x = rna_f(v.x); v.y = rna_f(v.y); v.z = rna_f(v.z); v.w = rna_f(v.w);
    ((float4*)dst)[i] = v;
}

// ---------------- init: counters only ----------------
__global__ void init_kernel() {
    if (threadIdx.x < NE) g_count[threadIdx.x] = 0;
}

// ---------------- router: 1 warp per token ----------------
__global__ void __launch_bounds__(256) router_kernel(
    const float* __restrict__ x, const float* __restrict__ Wr,
    const float* __restrict__ br)
{
    int warp = threadIdx.x >> 5;
    int lane = threadIdx.x & 31;
    int t = blockIdx.x * 8 + warp;
    if (t >= NT) return;

    const float* xr = x + (size_t)t * DIN;
    float acc[NE];
#pragma unroll
    for (int e = 0; e < NE; e++) acc[e] = 0.f;
    for (int d = lane; d < DIN; d += 32) {
        float xv = xr[d];
        const float* w = Wr + (size_t)d * NE;
#pragma unroll
        for (int e = 0; e < NE; e++) acc[e] += xv * w[e];
    }
#pragma unroll
    for (int e = 0; e < NE; e++) {
#pragma unroll
        for (int off = 16; off; off >>= 1)
            acc[e] += __shfl_xor_sync(0xffffffffu, acc[e], off);
    }
    if (lane == 0) {
        float logit[NE], p[NE];
        float mx = -1e30f;
#pragma unroll
        for (int e = 0; e < NE; e++) { logit[e] = acc[e] + br[e]; mx = fmaxf(mx, logit[e]); }
        float s = 0.f;
#pragma unroll
        for (int e = 0; e < NE; e++) { p[e] = expf(logit[e] - mx); s += p[e]; }
        float inv = 1.f / s;
#pragma unroll
        for (int e = 0; e < NE; e++) p[e] *= inv;
        int i0 = 0;
#pragma unroll
        for (int e = 1; e < NE; e++) if (p[e] > p[i0]) i0 = e;
        int i1 = (i0 == 0) ? 1 : 0;
#pragma unroll
        for (int e = 0; e < NE; e++) { if (e == i0) continue; if (p[e] > p[i1]) i1 = e; }
        int idx[2] = { i0, i1 };
#pragma unroll
        for (int k = 0; k < 2; k++) {
            int e = idx[k];
            int pos = atomicAdd(&g_count[e], 1);
            g_hrow[e][pos] = t * 2 + k;
            g_cwk[t][k]    = p[e];
        }
    }
}

// ============================================================================
// tf32 MMA tile core (R11). BM=128, BN=128, BK=32, 256 thr, 8 warps (2x4),
// warp tile 64x32. A pre-rounded + ldmatrix.x4; B cvt at fragment load.
// 2-stage cp.async pipeline, 2 syncs per K-tile.
// ============================================================================

template<int N_DIM>
__device__ __forceinline__ void load_tile(
    float* As, float* Bs, const float* __restrict__ Asrc_base,
    const int* s_row, const float* __restrict__ Bsrc,
    int k0, int tid, int a_src_ld)
{
    // A: 128 rows x 32 floats = 1024 float4; 4 per thread (gathered rows)
#pragma unroll
    for (int i = 0; i < 4; i++) {
        int c   = tid + i * 256;
        int row = c >> 3;
        int c4  = (c & 7) * 4;
        const float* src = Asrc_base + (size_t)s_row[row] * a_src_ld + k0 + c4;
        uint32_t dst = (uint32_t)__cvta_generic_to_shared(As + row * A_STRIDE + c4);
        CP_ASYNC16(dst, src);
    }
    // B: 32 rows x 128 floats = 1024 float4; 4 per thread
#pragma unroll
    for (int i = 0; i < 4; i++) {
        int c   = tid + i * 256;
        int row = c >> 5;
        int c4  = (c & 31) * 4;
        const float* src = Bsrc + (size_t)row * N_DIM + c4;
        uint32_t dst = (uint32_t)__cvta_generic_to_shared(Bs + row * B_STRIDE + c4);
        CP_ASYNC16(dst, src);
    }
    CP_COMMIT();
}

// A fragments via ldmatrix.x4 (mapping verified in R7/R11 runs)
__device__ __forceinline__ void compute_tile(
    uint32_t As_s, const float* Bs, float acc[4][4][4], int lane, int wm, int wn)
{
    int g  = lane >> 2;
    int t4 = lane & 3;
    int arow  = (lane & 7) + ((lane >> 3) & 1) * 8;  // row within 16-row frag
    int acol4 = (lane >> 4) * 4;                     // 0 or 4 (k-offset)
    uint32_t a_thread = As_s + (uint32_t)(((wm * 64 + arow) * A_STRIDE + acol4) * 4);

#pragma unroll
    for (int kk = 0; kk < 4; kk++) {
        int k = kk * 8;
        uint32_t af[4][4];
        uint32_t bf[4][2];
#pragma unroll
        for (int mi = 0; mi < 4; mi++)
            ldsm_x4(af[mi], a_thread + (uint32_t)(mi * 16 * A_STRIDE * 4 + k * 4));
#pragma unroll
        for (int ni = 0; ni < 4; ni++) {
            int col = wn * 32 + ni * 8 + g;
            bf[ni][0] = f2tf32(Bs[(k + t4    ) * B_STRIDE + col]);
            bf[ni][1] = f2tf32(Bs[(k + t4 + 4) * B_STRIDE + col]);
        }
#pragma unroll
        for (int mi = 0; mi < 4; mi++)
#pragma unroll
            for (int ni = 0; ni < 4; ni++)
                mma_tf32(acc[mi][ni], af[mi], bf[ni]);
    }
}

// ---------------- GEMM1: h = rna(relu(xr @ W1 + b1)) ----------------
__global__ void __launch_bounds__(256, 3) gemm1_kernel(
    const float* __restrict__ W1, const float* __restrict__ b1)
{
    extern __shared__ float smem[];
    float* As = smem;
    float* Bs = smem + 2 * A_BUF;

    int e = blockIdx.z;
    int count = g_count[e];
    int r0 = blockIdx.y * 128;
    if (r0 >= count) return;
    int n0 = blockIdx.x * 128;

    __shared__ int s_hrow[128];
    __shared__ int s_tok[128];

    int tid = threadIdx.x;
    if (tid < 128) {
        int r = r0 + tid;
        if (r < count) { int hr = g_hrow[e][r]; s_hrow[tid] = hr; s_tok[tid] = hr >> 1; }
        else           { s_hrow[tid] = -1;      s_tok[tid] = g_hrow[e][0] >> 1; }
    }
    __syncthreads();

    const float* W1e = W1 + (size_t)e * DIN * DHID;
    int lane = tid & 31, warp = tid >> 5;
    int wm = warp >> 2, wn = warp & 3;

    float acc[4][4][4];
#pragma unroll
    for (int a = 0; a < 4; a++)
#pragma unroll
        for (int b = 0; b < 4; b++)
#pragma unroll
            for (int c = 0; c < 4; c++) acc[a][b][c] = 0.f;

    const int KT = DIN / 32;
    load_tile<DHID>(As, Bs, &g_xr[0][0], s_tok, W1e + n0, 0, tid, DIN);
    for (int kt = 0; kt < KT; kt++) {
        if (kt + 1 < KT)
            load_tile<DHID>(As + ((kt + 1) & 1) * A_BUF, Bs + ((kt + 1) & 1) * B_BUF,
                            &g_xr[0][0], s_tok, W1e + (size_t)(kt + 1) * 32 * DHID + n0,
                            (kt + 1) * 32, tid, DIN);
        if (kt + 1 < KT) { CP_WAIT(1); } else { CP_WAIT(0); }
        __syncthreads();
        compute_tile((uint32_t)__cvta_generic_to_shared(As + (kt & 1) * A_BUF),
                     Bs + (kt & 1) * B_BUF, acc, lane, wm, wn);
        __syncthreads();
    }

    const float* b1e = b1 + (size_t)e * DHID + n0;
    int g = lane >> 2, t4 = lane & 3;
#pragma unroll
    for (int mi = 0; mi < 4; mi++) {
#pragma unroll
        for (int half = 0; half < 2; half++) {
            int m  = wm * 64 + mi * 16 + g + half * 8;
            int hr = s_hrow[m];
            if (hr < 0) continue;
#pragma unroll
            for (int ni = 0; ni < 4; ni++) {
                int col = wn * 32 + ni * 8 + t4 * 2;
                float c0 = acc[mi][ni][half * 2 + 0] + b1e[col];
                float c1 = acc[mi][ni][half * 2 + 1] + b1e[col + 1];
                float2 v = make_float2(rna_f(fmaxf(c0, 0.f)), rna_f(fmaxf(c1, 0.f)));
                *(float2*)(&g_h[hr][n0 + col]) = v;
            }
        }
    }
}

// ---------------- GEMM2: y[hrow] = h @ W2 + b2 (plain stores) ----------------
__global__ void __launch_bounds__(256, 3) gemm2_kernel(
    const float* __restrict__ W2, const float* __restrict__ b2)
{
    extern __shared__ float smem[];
    float* As = smem;
    float* Bs = smem + 2 * A_BUF;

    int e = blockIdx.z;
    int count = g_count[e];
    int r0 = blockIdx.y * 128;
    if (r0 >= count) return;
    int n0 = blockIdx.x * 128;

    __shared__ int s_hrow[128];

    int tid = threadIdx.x;
    if (tid < 128) {
        int r = r0 + tid;
        s_hrow[tid] = (r < count) ? g_hrow[e][r] : -1;
        if (s_hrow[tid] < 0) s_hrow[tid] = -1;
    }
    // padding rows need a valid gather source:
    __shared__ int s_tok2[128];
    if (tid < 128) s_tok2[tid] = (s_hrow[tid] >= 0) ? s_hrow[tid] : g_hrow[e][0];
    __syncthreads();

    const float* W2e = W2 + (size_t)e * DHID * DOUT;
    int lane = tid & 31, warp = tid >> 5;
    int wm = warp >> 2, wn = warp & 3;

    float acc[4][4][4];
#pragma unroll
    for (int a = 0; a < 4; a++)
#pragma unroll
        for (int b = 0; b < 4; b++)
#pragma unroll
            for (int c = 0; c < 4; c++) acc[a][b][c] = 0.f;

    const int KT = DHID / 32;
    load_tile<DOUT>(As, Bs, &g_h[0][0], s_tok2, W2e + n0, 0, tid, DHID);
    for (int kt = 0; kt < KT; kt++) {
        if (kt + 1 < KT)
            load_tile<DOUT>(As + ((kt + 1) & 1) * A_BUF, Bs + ((kt + 1) & 1) * B_BUF,
                            &g_h[0][0], s_tok2, W2e + (size_t)(kt + 1) * 32 * DOUT + n0,
                            (kt + 1) * 32, tid, DHID);
        if (kt + 1 < KT) { CP_WAIT(1); } else { CP_WAIT(0); }
        __syncthreads();
        compute_tile((uint32_t)__cvta_generic_to_shared(As + (kt & 1) * A_BUF),
                     Bs + (kt & 1) * B_BUF, acc, lane, wm, wn);
        __syncthreads();
    }

    const float* b2e = b2 + (size_t)e * DOUT + n0;
    int g = lane >> 2, t4 = lane & 3;
#pragma unroll
    for (int mi = 0; mi < 4; mi++) {
#pragma unroll
        for (int half = 0; half < 2; half++) {
            int m  = wm * 64 + mi * 16 + g + half * 8;
            int hr = s_hrow[m];
            if (hr < 0) continue;
#pragma unroll
            for (int ni = 0; ni < 4; ni++) {
                int col = wn * 32 + ni * 8 + t4 * 2;
                float2 v;
                v.x = acc[mi][ni][half * 2 + 0] + b2e[col];
                v.y = acc[mi][ni][half * 2 + 1] + b2e[col + 1];
                *(float2*)(&g_y[hr][n0 + col]) = v;
            }
        }
    }
}

// ---------------- combine: out[t] = cw0*y[2t] + cw1*y[2t+1] ----------------
__global__ void __launch_bounds__(256) combine_kernel(float* __restrict__ out) {
    int i = blockIdx.x * blockDim.x + threadIdx.x;      // float4 index
    int t  = i / (DOUT / 4);
    int c4 = (i % (DOUT / 4)) * 4;
    float w0 = g_cwk[t][0];
    float w1 = g_cwk[t][1];
    float4 a = *(const float4*)(&g_y[t * 2    ][c4]);
    float4 b = *(const float4*)(&g_y[t * 2 + 1][c4]);
    float4 o;
    o.x = w0 * a.x + w1 * b.x;
    o.y = w0 * a.y + w1 * b.y;
    o.z = w0 * a.z + w1 * b.z;
    o.w = w0 * a.w + w1 * b.w;
    ((float4*)out)[i] = o;
}

// ---------------- launch ----------------
extern "C" void kernel_launch(void* const* d_in, const int* in_sizes, int n_in,
                              void* d_out, int out_size) {
    const float* x  = (const float*)d_in[0];
    const float* Wr = (const float*)d_in[1];
    const float* br = (const float*)d_in[2];
    const float* W1 = (const float*)d_in[3];
    const float* b1 = (const float*)d_in[4];
    const float* W2 = (const float*)d_in[5];
    const float* b2 = (const float*)d_in[6];
    float* out = (float*)d_out;

    const int smem_bytes = SMEM_FLOATS * 4;   // 70656
    cudaFuncSetAttribute(gemm1_kernel, cudaFuncAttributeMaxDynamicSharedMemorySize, smem_bytes);
    cudaFuncSetAttribute(gemm2_kernel, cudaFuncAttributeMaxDynamicSharedMemorySize, smem_bytes);

    float* xr;  cudaGetSymbolAddress((void**)&xr, g_xr);

    round_x_kernel<<<NT * DIN / 1024, 256>>>(x, xr);
    init_kernel<<<1, 32>>>();
    router_kernel<<<NT / 8, 256>>>(x, Wr, br);
    gemm1_kernel<<<dim3(DHID / 128, NT / 128, NE), 256, smem_bytes>>>(W1, b1);
    gemm2_kernel<<<dim3(DOUT / 128, NT / 128, NE), 256, smem_bytes>>>(W2, b2);
    combine_kernel<<<NT * DOUT / 4 / 256, 256>>>(out);
}

// round 15
// speedup vs baseline: 2.0715x; 2.0715x over previous
#include <cuda_runtime.h>
#include <cstdint>

#define NT   2048
#define DIN  1024
#define DHID 4096
#define DOUT 1024
#define NE   8

// ---------------- device scratch ----------------
__device__ int   g_count[NE];
__device__ int   g_hrow[NE][NT];     // hrow = token*2 + k
__device__ float g_cwk[NT][2];       // combine weight [token][k] (deterministic index)
__device__ float g_h[NT * 2][DHID];  // hidden acts (tf32-rounded at write)
__device__ float g_y[NT * 2][DOUT];  // expert outputs before combine
__device__ float g_xr[NT][DIN];      // x (tf32-rounded)

// ---------------- helpers ----------------
__device__ __forceinline__ float rna_f(float f) {
    uint32_t u;
    asm volatile("cvt.rna.tf32.f32 %0, %1;" : "=r"(u) : "f"(f));
    return __uint_as_float(u);
}
__device__ __forceinline__ uint32_t f2tf32(float f) {
    uint32_t u;
    asm volatile("cvt.rna.tf32.f32 %0, %1;" : "=r"(u) : "f"(f));
    return u;
}
__device__ __forceinline__ void mma_tf32(float* c, const uint32_t* a, const uint32_t* b) {
    asm volatile(
        "mma.sync.aligned.m16n8k8.row.col.f32.tf32.tf32.f32 "
        "{%0,%1,%2,%3}, {%4,%5,%6,%7}, {%8,%9}, {%0,%1,%2,%3};"
        : "+f"(c[0]), "+f"(c[1]), "+f"(c[2]), "+f"(c[3])
        : "r"(a[0]), "r"(a[1]), "r"(a[2]), "r"(a[3]), "r"(b[0]), "r"(b[1]));
}
__device__ __forceinline__ void ldsm_x4(uint32_t* r, uint32_t saddr) {
    asm volatile("ldmatrix.sync.aligned.m8n8.x4.shared.b16 {%0,%1,%2,%3}, [%4];"
        : "=r"(r[0]), "=r"(r[1]), "=r"(r[2]), "=r"(r[3]) : "r"(saddr));
}
#define CP_ASYNC16(dst, src) \
    asm volatile("cp.async.cg.shared.global [%0], [%1], 16;\n" :: "r"(dst), "l"(src))
#define CP_COMMIT() asm volatile("cp.async.commit_group;\n" ::)
#define CP_WAIT(n)  asm volatile("cp.async.wait_group %0;\n" :: "n"(n))

// smem layout (identical to R2/R6/R11)
#define A_STRIDE 36     // 32 + 4 pad (floats)
#define B_STRIDE 136    // 128 + 8 pad (floats)
#define A_BUF (128 * A_STRIDE)
#define B_BUF (32 * B_STRIDE)
#define SMEM_FLOATS (2 * A_BUF + 2 * B_BUF)   // 17664 floats = 70656 B

// ---------------- prepass: round x (8 MB, ~4us) ----------------
__global__ void round_x_kernel(const float* __restrict__ src, float* __restrict__ dst) {
    int i = blockIdx.x * blockDim.x + threadIdx.x;
    float4 v = ((const float4*)src)[i];
    v.x = rna_f(v.x); v.y = rna_f(v.y); v.z = rna_f(v.z); v.w = rna_f(v.w);
    ((float4*)dst)[i] = v;
}

// ---------------- init: counters only ----------------
__global__ void init_kernel() {
    if (threadIdx.x < NE) g_count[threadIdx.x] = 0;
}

// ---------------- router: 1 warp per token ----------------
__global__ void __launch_bounds__(256) router_kernel(
    const float* __restrict__ x, const float* __restrict__ Wr,
    const float* __restrict__ br)
{
    int warp = threadIdx.x >> 5;
    int lane = threadIdx.x & 31;
    int t = blockIdx.x * 8 + warp;
    if (t >= NT) return;

    const float* xr = x + (size_t)t * DIN;
    float acc[NE];
#pragma unroll
    for (int e = 0; e < NE; e++) acc[e] = 0.f;
    for (int d = lane; d < DIN; d += 32) {
        float xv = xr[d];
        const float* w = Wr + (size_t)d * NE;
#pragma unroll
        for (int e = 0; e < NE; e++) acc[e] += xv * w[e];
    }
#pragma unroll
    for (int e = 0; e < NE; e++) {
#pragma unroll
        for (int off = 16; off; off >>= 1)
            acc[e] += __shfl_xor_sync(0xffffffffu, acc[e], off);
    }
    if (lane == 0) {
        float logit[NE], p[NE];
        float mx = -1e30f;
#pragma unroll
        for (int e = 0; e < NE; e++) { logit[e] = acc[e] + br[e]; mx = fmaxf(mx, logit[e]); }
        float s = 0.f;
#pragma unroll
        for (int e = 0; e < NE; e++) { p[e] = expf(logit[e] - mx); s += p[e]; }
        float inv = 1.f / s;
#pragma unroll
        for (int e = 0; e < NE; e++) p[e] *= inv;
        int i0 = 0;
#pragma unroll
        for (int e = 1; e < NE; e++) if (p[e] > p[i0]) i0 = e;
        int i1 = (i0 == 0) ? 1 : 0;
#pragma unroll
        for (int e = 0; e < NE; e++) { if (e == i0) continue; if (p[e] > p[i1]) i1 = e; }
        int idx[2] = { i0, i1 };
#pragma unroll
        for (int k = 0; k < 2; k++) {
            int e = idx[k];
            int pos = atomicAdd(&g_count[e], 1);
            g_hrow[e][pos] = t * 2 + k;
            g_cwk[t][k]    = p[e];
        }
    }
}

// ============================================================================
// tf32 MMA tile core (R11, regs ~94, no occupancy forcing). BM=128, BN=128,
// BK=32, 256 thr, 8 warps (2x4), warp tile 64x32. A pre-rounded + ldmatrix.x4;
// B cvt at fragment load. 2-stage cp.async pipeline, 2 syncs per K-tile.
// ============================================================================

template<int N_DIM>
__device__ __forceinline__ void load_tile(
    float* As, float* Bs, const float* __restrict__ Asrc_base,
    const int* s_row, const float* __restrict__ Bsrc,
    int k0, int tid, int a_src_ld)
{
    // A: 128 rows x 32 floats = 1024 float4; 4 per thread (gathered rows)
#pragma unroll
    for (int i = 0; i < 4; i++) {
        int c   = tid + i * 256;
        int row = c >> 3;
        int c4  = (c & 7) * 4;
        const float* src = Asrc_base + (size_t)s_row[row] * a_src_ld + k0 + c4;
        uint32_t dst = (uint32_t)__cvta_generic_to_shared(As + row * A_STRIDE + c4);
        CP_ASYNC16(dst, src);
    }
    // B: 32 rows x 128 floats = 1024 float4; 4 per thread
#pragma unroll
    for (int i = 0; i < 4; i++) {
        int c   = tid + i * 256;
        int row = c >> 5;
        int c4  = (c & 31) * 4;
        const float* src = Bsrc + (size_t)row * N_DIM + c4;
        uint32_t dst = (uint32_t)__cvta_generic_to_shared(Bs + row * B_STRIDE + c4);
        CP_ASYNC16(dst, src);
    }
    CP_COMMIT();
}

// A fragments via ldmatrix.x4 (mapping verified in R7/R11 runs)
__device__ __forceinline__ void compute_tile(
    uint32_t As_s, const float* Bs, float acc[4][4][4], int lane, int wm, int wn)
{
    int g  = lane >> 2;
    int t4 = lane & 3;
    int arow  = (lane & 7) + ((lane >> 3) & 1) * 8;  // row within 16-row frag
    int acol4 = (lane >> 4) * 4;                     // 0 or 4 (k-offset)
    uint32_t a_thread = As_s + (uint32_t)(((wm * 64 + arow) * A_STRIDE + acol4) * 4);

#pragma unroll
    for (int kk = 0; kk < 4; kk++) {
        int k = kk * 8;
        uint32_t af[4][4];
        uint32_t bf[4][2];
#pragma unroll
        for (int mi = 0; mi < 4; mi++)
            ldsm_x4(af[mi], a_thread + (uint32_t)(mi * 16 * A_STRIDE * 4 + k * 4));
#pragma unroll
        for (int ni = 0; ni < 4; ni++) {
            int col = wn * 32 + ni * 8 + g;
            bf[ni][0] = f2tf32(Bs[(k + t4    ) * B_STRIDE + col]);
            bf[ni][1] = f2tf32(Bs[(k + t4 + 4) * B_STRIDE + col]);
        }
#pragma unroll
        for (int mi = 0; mi < 4; mi++)
#pragma unroll
            for (int ni = 0; ni < 4; ni++)
                mma_tf32(acc[mi][ni], af[mi], bf[ni]);
    }
}

// ---------------- GEMM1: h = rna(relu(xr @ W1 + b1)) ----------------
__global__ void __launch_bounds__(256) gemm1_kernel(
    const float* __restrict__ W1, const float* __restrict__ b1)
{
    extern __shared__ float smem[];
    float* As = smem;
    float* Bs = smem + 2 * A_BUF;

    int e = blockIdx.z;
    int count = g_count[e];
    int r0 = blockIdx.y * 128;
    if (r0 >= count) return;
    int n0 = blockIdx.x * 128;

    __shared__ int s_hrow[128];
    __shared__ int s_tok[128];

    int tid = threadIdx.x;
    if (tid < 128) {
        int r = r0 + tid;
        if (r < count) { int hr = g_hrow[e][r]; s_hrow[tid] = hr; s_tok[tid] = hr >> 1; }
        else           { s_hrow[tid] = -1;      s_tok[tid] = g_hrow[e][0] >> 1; }
    }
    __syncthreads();

    const float* W1e = W1 + (size_t)e * DIN * DHID;
    int lane = tid & 31, warp = tid >> 5;
    int wm = warp >> 2, wn = warp & 3;

    float acc[4][4][4];
#pragma unroll
    for (int a = 0; a < 4; a++)
#pragma unroll
        for (int b = 0; b < 4; b++)
#pragma unroll
            for (int c = 0; c < 4; c++) acc[a][b][c] = 0.f;

    const int KT = DIN / 32;
    load_tile<DHID>(As, Bs, &g_xr[0][0], s_tok, W1e + n0, 0, tid, DIN);
    for (int kt = 0; kt < KT; kt++) {
        if (kt + 1 < KT)
            load_tile<DHID>(As + ((kt + 1) & 1) * A_BUF, Bs + ((kt + 1) & 1) * B_BUF,
                            &g_xr[0][0], s_tok, W1e + (size_t)(kt + 1) * 32 * DHID + n0,
                            (kt + 1) * 32, tid, DIN);
        if (kt + 1 < KT) { CP_WAIT(1); } else { CP_WAIT(0); }
        __syncthreads();
        compute_tile((uint32_t)__cvta_generic_to_shared(As + (kt & 1) * A_BUF),
                     Bs + (kt & 1) * B_BUF, acc, lane, wm, wn);
        __syncthreads();
    }

    const float* b1e = b1 + (size_t)e * DHID + n0;
    int g = lane >> 2, t4 = lane & 3;
#pragma unroll
    for (int mi = 0; mi < 4; mi++) {
#pragma unroll
        for (int half = 0; half < 2; half++) {
            int m  = wm * 64 + mi * 16 + g + half * 8;
            int hr = s_hrow[m];
            if (hr < 0) continue;
#pragma unroll
            for (int ni = 0; ni < 4; ni++) {
                int col = wn * 32 + ni * 8 + t4 * 2;
                float c0 = acc[mi][ni][half * 2 + 0] + b1e[col];
                float c1 = acc[mi][ni][half * 2 + 1] + b1e[col + 1];
                float2 v = make_float2(rna_f(fmaxf(c0, 0.f)), rna_f(fmaxf(c1, 0.f)));
                *(float2*)(&g_h[hr][n0 + col]) = v;
            }
        }
    }
}

// ---------------- GEMM2: y[hrow] = h @ W2 + b2 (plain stores) ----------------
__global__ void __launch_bounds__(256) gemm2_kernel(
    const float* __restrict__ W2, const float* __restrict__ b2)
{
    extern __shared__ float smem[];
    float* As = smem;
    float* Bs = smem + 2 * A_BUF;

    int e = blockIdx.z;
    int count = g_count[e];
    int r0 = blockIdx.y * 128;
    if (r0 >= count) return;
    int n0 = blockIdx.x * 128;

    __shared__ int s_hrow[128];
    __shared__ int s_tok2[128];

    int tid = threadIdx.x;
    if (tid < 128) {
        int r = r0 + tid;
        int hr = (r < count) ? g_hrow[e][r] : -1;
        s_hrow[tid] = hr;
        s_tok2[tid] = (hr >= 0) ? hr : g_hrow[e][0];
    }
    __syncthreads();

    const float* W2e = W2 + (size_t)e * DHID * DOUT;
    int lane = tid & 31, warp = tid >> 5;
    int wm = warp >> 2, wn = warp & 3;

    float acc[4][4][4];
#pragma unroll
    for (int a = 0; a < 4; a++)
#pragma unroll
        for (int b = 0; b < 4; b++)
#pragma unroll
            for (int c = 0; c < 4; c++) acc[a][b][c] = 0.f;

    const int KT = DHID / 32;
    load_tile<DOUT>(As, Bs, &g_h[0][0], s_tok2, W2e + n0, 0, tid, DHID);
    for (int kt = 0; kt < KT; kt++) {
        if (kt + 1 < KT)
            load_tile<DOUT>(As + ((kt + 1) & 1) * A_BUF, Bs + ((kt + 1) & 1) * B_BUF,
                            &g_h[0][0], s_tok2, W2e + (size_t)(kt + 1) * 32 * DOUT + n0,
                            (kt + 1) * 32, tid, DHID);
        if (kt + 1 < KT) { CP_WAIT(1); } else { CP_WAIT(0); }
        __syncthreads();
        compute_tile((uint32_t)__cvta_generic_to_shared(As + (kt & 1) * A_BUF),
                     Bs + (kt & 1) * B_BUF, acc, lane, wm, wn);
        __syncthreads();
    }

    const float* b2e = b2 + (size_t)e * DOUT + n0;
    int g = lane >> 2, t4 = lane & 3;
#pragma unroll
    for (int mi = 0; mi < 4; mi++) {
#pragma unroll
        for (int half = 0; half < 2; half++) {
            int m  = wm * 64 + mi * 16 + g + half * 8;
            int hr = s_hrow[m];
            if (hr < 0) continue;
#pragma unroll
            for (int ni = 0; ni < 4; ni++) {
                int col = wn * 32 + ni * 8 + t4 * 2;
                float2 v;
                v.x = acc[mi][ni][half * 2 + 0] + b2e[col];
                v.y = acc[mi][ni][half * 2 + 1] + b2e[col + 1];
                *(float2*)(&g_y[hr][n0 + col]) = v;
            }
        }
    }
}

// ---------------- combine: out[t] = cw0*y[2t] + cw1*y[2t+1] ----------------
__global__ void __launch_bounds__(256) combine_kernel(float* __restrict__ out) {
    int i = blockIdx.x * blockDim.x + threadIdx.x;      // float4 index
    int t  = i / (DOUT / 4);
    int c4 = (i % (DOUT / 4)) * 4;
    float w0 = g_cwk[t][0];
    float w1 = g_cwk[t][1];
    float4 a = *(const float4*)(&g_y[t * 2    ][c4]);
    float4 b = *(const float4*)(&g_y[t * 2 + 1][c4]);
    float4 o;
    o.x = w0 * a.x + w1 * b.x;
    o.y = w0 * a.y + w1 * b.y;
    o.z = w0 * a.z + w1 * b.z;
    o.w = w0 * a.w + w1 * b.w;
    ((float4*)out)[i] = o;
}

// ---------------- launch ----------------
extern "C" void kernel_launch(void* const* d_in, const int* in_sizes, int n_in,
                              void* d_out, int out_size) {
    const float* x  = (const float*)d_in[0];
    const float* Wr = (const float*)d_in[1];
    const float* br = (const float*)d_in[2];
    const float* W1 = (const float*)d_in[3];
    const float* b1 = (const float*)d_in[4];
    const float* W2 = (const float*)d_in[5];
    const float* b2 = (const float*)d_in[6];
    float* out = (float*)d_out;

    const int smem_bytes = SMEM_FLOATS * 4;   // 70656
    cudaFuncSetAttribute(gemm1_kernel, cudaFuncAttributeMaxDynamicSharedMemorySize, smem_bytes);
    cudaFuncSetAttribute(gemm2_kernel, cudaFuncAttributeMaxDynamicSharedMemorySize, smem_bytes);

    float* xr;  cudaGetSymbolAddress((void**)&xr, g_xr);

    round_x_kernel<<<NT * DIN / 1024, 256>>>(x, xr);
    init_kernel<<<1, 32>>>();
    router_kernel<<<NT / 8, 256>>>(x, Wr, br);
    gemm1_kernel<<<dim3(DHID / 128, NT / 128, NE), 256, smem_bytes>>>(W1, b1);
    gemm2_kernel<<<dim3(DOUT / 128, NT / 128, NE), 256, smem_bytes>>>(W2, b2);
    combine_kernel<<<NT * DOUT / 4 / 256, 256>>>(out);
}